// round 7
// baseline (speedup 1.0000x reference)
#include <cuda_runtime.h>
#include <cuda_fp16.h>
#include <cuda_bf16.h>

// dense_image_warp, B=8 H=1024 W=768 C=3 fp32.
// R6 (resubmit): pair-fp16 scratch (one LDG.128 fetches both horizontal taps
// of a bilinear row) + 4 pixels/thread in BOTH kernels for vectorized flow
// loads (2x LDG.128), vectorized stores (3x STG.128), and 8-deep gather MLP.

#define WB 8
#define WH 1024
#define WW 768
#define NPIX (WB * WH * WW)          // 6,291,456
#define NGRP (NPIX / 4)              // 1,572,864

__device__ __align__(16) uint4 g_pair[NPIX];   // ~100.7 MB module-static scratch

__device__ __forceinline__ float2 h2f(unsigned u) {
    __half2 h = *reinterpret_cast<__half2*>(&u);
    return __half22float2(h);
}

__global__ void __launch_bounds__(256) pad_pair_kernel(const float* __restrict__ img)
{
    int i = blockIdx.x * blockDim.x + threadIdx.x;
    if (i >= NGRP) return;

    // pixels 4i..4i+3 = floats [12i, 12i+12); also need pixel 4i+4
    const float4* src = reinterpret_cast<const float4*>(img) + 3 * (size_t)i;
    float4 a = __ldg(src);       // p0.rgb, p1.r
    float4 b = __ldg(src + 1);   // p1.gb,  p2.rg
    float4 c = __ldg(src + 2);   // p2.b,   p3.rgb
    float4 d;
    if (i + 1 < NGRP) {
        d = __ldg(src + 3);      // p4.rgb, p5.r
    } else {
        d = make_float4(c.y, c.z, c.w, 0.f);   // duplicate last pixel
    }

    uint4* dst = g_pair + 4 * (size_t)i;
    // pair slot for pixel p holds {p.r,p.g | p.b,(p+1).r | (p+1).g,(p+1).b | pad}
    __half2 h;
    uint4 v; v.w = 0u;

    h = __floats2half2_rn(a.x, a.y); v.x = *reinterpret_cast<unsigned*>(&h);
    h = __floats2half2_rn(a.z, a.w); v.y = *reinterpret_cast<unsigned*>(&h);
    h = __floats2half2_rn(b.x, b.y); v.z = *reinterpret_cast<unsigned*>(&h);
    dst[0] = v;

    h = __floats2half2_rn(a.w, b.x); v.x = *reinterpret_cast<unsigned*>(&h);
    h = __floats2half2_rn(b.y, b.z); v.y = *reinterpret_cast<unsigned*>(&h);
    h = __floats2half2_rn(b.w, c.x); v.z = *reinterpret_cast<unsigned*>(&h);
    dst[1] = v;

    h = __floats2half2_rn(b.z, b.w); v.x = *reinterpret_cast<unsigned*>(&h);
    h = __floats2half2_rn(c.x, c.y); v.y = *reinterpret_cast<unsigned*>(&h);
    h = __floats2half2_rn(c.z, c.w); v.z = *reinterpret_cast<unsigned*>(&h);
    dst[2] = v;

    h = __floats2half2_rn(c.y, c.z); v.x = *reinterpret_cast<unsigned*>(&h);
    h = __floats2half2_rn(c.w, d.x); v.y = *reinterpret_cast<unsigned*>(&h);
    h = __floats2half2_rn(d.y, d.z); v.z = *reinterpret_cast<unsigned*>(&h);
    dst[3] = v;
}

__global__ void __launch_bounds__(256) warp_kernel(
    const float* __restrict__ flow,
    float* __restrict__ out)
{
    int g = blockIdx.x * blockDim.x + threadIdx.x;
    if (g >= NGRP) return;

    int idx0 = g * 4;
    int xb = idx0 % WW;            // W divisible by 4 -> all 4 pixels same row
    int t = idx0 / WW;
    int y = t & (WH - 1);
    int b = t >> 10;

    const float4* fp = reinterpret_cast<const float4*>(flow) + 2 * (size_t)g;
    float4 fA = __ldg(fp);
    float4 fB = __ldg(fp + 1);
    float dy[4] = {fA.x, fA.z, fB.x, fB.z};
    float dx[4] = {fA.y, fA.w, fB.y, fB.w};

    const uint4* img_b = g_pair + (size_t)b * (WH * WW);

    uint4 tp[4], bt[4];
    float ax[4], ay[4];
#pragma unroll
    for (int k = 0; k < 4; k++) {
        float qy = (float)y - dy[k];
        float qx = (float)(xb + k) - dx[k];
        float y0f = fminf(fmaxf(floorf(qy), 0.0f), (float)(WH - 2));
        float x0f = fminf(fmaxf(floorf(qx), 0.0f), (float)(WW - 2));
        ay[k] = fminf(fmaxf(qy - y0f, 0.0f), 1.0f);
        ax[k] = fminf(fmaxf(qx - x0f, 0.0f), 1.0f);
        const uint4* p = img_b + (int)y0f * WW + (int)x0f;
        tp[k] = __ldg(p);          // taps (y0,x0),(y0,x0+1)
        bt[k] = __ldg(p + WW);     // taps (y0+1,x0),(y0+1,x0+1)
    }

    float4 o[3];
    float* os = reinterpret_cast<float*>(o);
#pragma unroll
    for (int k = 0; k < 4; k++) {
        float2 t0 = h2f(tp[k].x);   // tl.r tl.g
        float2 t1 = h2f(tp[k].y);   // tl.b tr.r
        float2 t2 = h2f(tp[k].z);   // tr.g tr.b
        float2 u0 = h2f(bt[k].x);
        float2 u1 = h2f(bt[k].y);
        float2 u2 = h2f(bt[k].z);

        float topr = t0.x + ax[k] * (t1.y - t0.x);
        float topg = t0.y + ax[k] * (t2.x - t0.y);
        float topb = t1.x + ax[k] * (t2.y - t1.x);
        float botr = u0.x + ax[k] * (u1.y - u0.x);
        float botg = u0.y + ax[k] * (u2.x - u0.y);
        float botb = u1.x + ax[k] * (u2.y - u1.x);

        os[3 * k + 0] = topr + ay[k] * (botr - topr);
        os[3 * k + 1] = topg + ay[k] * (botg - topg);
        os[3 * k + 2] = topb + ay[k] * (botb - topb);
    }

    float4* op = reinterpret_cast<float4*>(out) + 3 * (size_t)g;
    op[0] = o[0];
    op[1] = o[1];
    op[2] = o[2];
}

extern "C" void kernel_launch(void* const* d_in, const int* in_sizes, int n_in,
                              void* d_out, int out_size)
{
    const float* image = (const float*)d_in[0];
    const float* flow  = (const float*)d_in[1];
    float* out = (float*)d_out;

    const int threads = 256;
    const int blocks = (NGRP + threads - 1) / threads;

    pad_pair_kernel<<<blocks, threads>>>(image);
    warp_kernel<<<blocks, threads>>>(flow, out);
}

// round 8
// speedup vs baseline: 1.1509x; 1.1509x over previous
#include <cuda_runtime.h>
#include <cuda_fp16.h>
#include <cuda_bf16.h>

// dense_image_warp, B=8 H=1024 W=768 C=3 fp32.
// R8: pair-fp16 scratch (one LDG.128 fetches both horizontal taps of a
// bilinear tap-row). Warp kernel does 2 pixels/thread with ALL-SCALAR locals
// (R6 showed indexed locals -> spills/pressure): 1x LDG.128 flow, 4 batched
// uint4 gathers, 3x STG.64 out. Pad kernel reverted to the proven R5 version.

#define WB 8
#define WH 1024
#define WW 768
#define NPIX (WB * WH * WW)          // 6,291,456
#define NPAIR (NPIX / 2)             // 3,145,728

__device__ __align__(16) uint4 g_pair[NPIX];   // ~100.7 MB module-static scratch

__device__ __forceinline__ float2 h2f(unsigned u) {
    __half2 h = *reinterpret_cast<__half2*>(&u);
    return __half22float2(h);
}

__global__ void __launch_bounds__(256) pad_pair_kernel(const float* __restrict__ img)
{
    int i = blockIdx.x * blockDim.x + threadIdx.x;
    if (i >= NPIX) return;

    const float* p = img + 3ull * (unsigned)i;
    float r0 = __ldg(p);
    float g0 = __ldg(p + 1);
    float b0 = __ldg(p + 2);

    int j = (i + 1 < NPIX) ? (i + 1) : i;
    const float* q = img + 3ull * (unsigned)j;
    float r1 = __ldg(q);
    float g1 = __ldg(q + 1);
    float b1 = __ldg(q + 2);

    __half2 h0 = __floats2half2_rn(r0, g0);
    __half2 h1 = __floats2half2_rn(b0, r1);
    __half2 h2 = __floats2half2_rn(g1, b1);

    uint4 v;
    v.x = *reinterpret_cast<unsigned*>(&h0);
    v.y = *reinterpret_cast<unsigned*>(&h1);
    v.z = *reinterpret_cast<unsigned*>(&h2);
    v.w = 0u;
    g_pair[i] = v;
}

__global__ void __launch_bounds__(256) warp_kernel(
    const float* __restrict__ flow,
    float* __restrict__ out)
{
    int g = blockIdx.x * blockDim.x + threadIdx.x;
    if (g >= NPAIR) return;

    int idx0 = g * 2;
    int x = idx0 % WW;             // even; W even -> both pixels on same row
    int t = idx0 / WW;
    int y = t & (WH - 1);
    int b = t >> 10;

    float4 f = __ldg(reinterpret_cast<const float4*>(flow) + g);
    // pixel A: dy=f.x dx=f.y ; pixel B: dy=f.z dx=f.w

    const uint4* img_b = g_pair + (size_t)b * (WH * WW);
    float yf = (float)y;

    // ---- addresses + alphas for both pixels (scalar) ----
    float qyA = yf - f.x;
    float qxA = (float)x - f.y;
    float y0fA = fminf(fmaxf(floorf(qyA), 0.0f), (float)(WH - 2));
    float x0fA = fminf(fmaxf(floorf(qxA), 0.0f), (float)(WW - 2));
    float ayA = fminf(fmaxf(qyA - y0fA, 0.0f), 1.0f);
    float axA = fminf(fmaxf(qxA - x0fA, 0.0f), 1.0f);
    const uint4* pA = img_b + (int)y0fA * WW + (int)x0fA;

    float qyB = yf - f.z;
    float qxB = (float)(x + 1) - f.w;
    float y0fB = fminf(fmaxf(floorf(qyB), 0.0f), (float)(WH - 2));
    float x0fB = fminf(fmaxf(floorf(qxB), 0.0f), (float)(WW - 2));
    float ayB = fminf(fmaxf(qyB - y0fB, 0.0f), 1.0f);
    float axB = fminf(fmaxf(qxB - x0fB, 0.0f), 1.0f);
    const uint4* pB = img_b + (int)y0fB * WW + (int)x0fB;

    // ---- 4 batched gathers (max MLP) ----
    uint4 tA = __ldg(pA);
    uint4 uA = __ldg(pA + WW);
    uint4 tB = __ldg(pB);
    uint4 uB = __ldg(pB + WW);

    // ---- pixel A lerp ----
    float2 a0 = h2f(tA.x), a1 = h2f(tA.y), a2 = h2f(tA.z);
    float2 c0 = h2f(uA.x), c1 = h2f(uA.y), c2 = h2f(uA.z);
    float toprA = a0.x + axA * (a1.y - a0.x);
    float topgA = a0.y + axA * (a2.x - a0.y);
    float topbA = a1.x + axA * (a2.y - a1.x);
    float botrA = c0.x + axA * (c1.y - c0.x);
    float botgA = c0.y + axA * (c2.x - c0.y);
    float botbA = c1.x + axA * (c2.y - c1.x);
    float orA = toprA + ayA * (botrA - toprA);
    float ogA = topgA + ayA * (botgA - topgA);
    float obA = topbA + ayA * (botbA - topbA);

    // ---- pixel B lerp ----
    float2 b0v = h2f(tB.x), b1v = h2f(tB.y), b2v = h2f(tB.z);
    float2 d0 = h2f(uB.x), d1 = h2f(uB.y), d2 = h2f(uB.z);
    float toprB = b0v.x + axB * (b1v.y - b0v.x);
    float topgB = b0v.y + axB * (b2v.x - b0v.y);
    float topbB = b1v.x + axB * (b2v.y - b1v.x);
    float botrB = d0.x + axB * (d1.y - d0.x);
    float botgB = d0.y + axB * (d2.x - d0.y);
    float botbB = d1.x + axB * (d2.y - d1.x);
    float orB = toprB + ayB * (botrB - toprB);
    float ogB = topgB + ayB * (botgB - topgB);
    float obB = topbB + ayB * (botbB - topbB);

    // ---- 3x STG.64 (byte offset 24g, 8B-aligned) ----
    float2* op = reinterpret_cast<float2*>(out + 6ull * (unsigned)g);
    op[0] = make_float2(orA, ogA);
    op[1] = make_float2(obA, orB);
    op[2] = make_float2(ogB, obB);
}

extern "C" void kernel_launch(void* const* d_in, const int* in_sizes, int n_in,
                              void* d_out, int out_size)
{
    const float* image = (const float*)d_in[0];
    const float* flow  = (const float*)d_in[1];
    float* out = (float*)d_out;

    const int threads = 256;

    pad_pair_kernel<<<(NPIX + threads - 1) / threads, threads>>>(image);
    warp_kernel<<<(NPAIR + threads - 1) / threads, threads>>>(flow, out);
}

// round 9
// speedup vs baseline: 1.2096x; 1.0510x over previous
#include <cuda_runtime.h>
#include <cuda_fp16.h>
#include <cuda_bf16.h>

// dense_image_warp, B=8 H=1024 W=768 C=3 fp32.
// R9: pair-fp16 scratch (R5 layout: one LDG.128 = both horizontal taps).
// Warp kernel: each thread processes pixel i AND pixel i+NPIX/2 (same (y,x),
// batches b and b+4). Per-instruction warp footprint stays 32 ADJACENT pixels
// (the R5 optimum for lines/instruction), but per-thread gather MLP doubles
// (4 independent LDG.128 in flight) to close the L1 utilization gap
// (73.7% -> ~85%+). All-scalar locals; no arrays (R6 spill lesson).

#define WB 8
#define WH 1024
#define WW 768
#define NPIX (WB * WH * WW)          // 6,291,456
#define NHALF (NPIX / 2)             // 3,145,728
#define PLANE (WH * WW)              // 786,432

__device__ __align__(16) uint4 g_pair[NPIX];   // ~100.7 MB module-static scratch

__device__ __forceinline__ float2 h2f(unsigned u) {
    __half2 h = *reinterpret_cast<__half2*>(&u);
    return __half22float2(h);
}

__global__ void __launch_bounds__(256) pad_pair_kernel(const float* __restrict__ img)
{
    int i = blockIdx.x * blockDim.x + threadIdx.x;
    if (i >= NPIX) return;

    const float* p = img + 3ull * (unsigned)i;
    float r0 = __ldg(p);
    float g0 = __ldg(p + 1);
    float b0 = __ldg(p + 2);

    int j = (i + 1 < NPIX) ? (i + 1) : i;
    const float* q = img + 3ull * (unsigned)j;
    float r1 = __ldg(q);
    float g1 = __ldg(q + 1);
    float b1 = __ldg(q + 2);

    __half2 h0 = __floats2half2_rn(r0, g0);
    __half2 h1 = __floats2half2_rn(b0, r1);
    __half2 h2 = __floats2half2_rn(g1, b1);

    uint4 v;
    v.x = *reinterpret_cast<unsigned*>(&h0);
    v.y = *reinterpret_cast<unsigned*>(&h1);
    v.z = *reinterpret_cast<unsigned*>(&h2);
    v.w = 0u;
    g_pair[i] = v;
}

__global__ void __launch_bounds__(256) warp_kernel(
    const float* __restrict__ flow,
    float* __restrict__ out)
{
    int i = blockIdx.x * blockDim.x + threadIdx.x;
    if (i >= NHALF) return;

    int x = i % WW;
    int t = i / WW;
    int y = t & (WH - 1);
    int b = t >> 10;               // 0..3 ; far pixel is batch b+4

    float2 fA = __ldg(reinterpret_cast<const float2*>(flow) + i);
    float2 fB = __ldg(reinterpret_cast<const float2*>(flow) + i + NHALF);

    float yf = (float)y;
    float xf = (float)x;

    // ---- addresses + alphas (scalar, both pixels) ----
    float qyA = yf - fA.x;
    float qxA = xf - fA.y;
    float y0fA = fminf(fmaxf(floorf(qyA), 0.0f), (float)(WH - 2));
    float x0fA = fminf(fmaxf(floorf(qxA), 0.0f), (float)(WW - 2));
    float ayA = fminf(fmaxf(qyA - y0fA, 0.0f), 1.0f);
    float axA = fminf(fmaxf(qxA - x0fA, 0.0f), 1.0f);
    const uint4* pA = g_pair + (size_t)b * PLANE + (int)y0fA * WW + (int)x0fA;

    float qyB = yf - fB.x;
    float qxB = xf - fB.y;
    float y0fB = fminf(fmaxf(floorf(qyB), 0.0f), (float)(WH - 2));
    float x0fB = fminf(fmaxf(floorf(qxB), 0.0f), (float)(WW - 2));
    float ayB = fminf(fmaxf(qyB - y0fB, 0.0f), 1.0f);
    float axB = fminf(fmaxf(qxB - x0fB, 0.0f), 1.0f);
    const uint4* pB = g_pair + (size_t)(b + 4) * PLANE + (int)y0fB * WW + (int)x0fB;

    // ---- 4 independent gathers, all issued before any use (MLP=4) ----
    uint4 tA = __ldg(pA);
    uint4 uA = __ldg(pA + WW);
    uint4 tB = __ldg(pB);
    uint4 uB = __ldg(pB + WW);

    // ---- pixel A ----
    float2 a0 = h2f(tA.x), a1 = h2f(tA.y), a2 = h2f(tA.z);
    float2 c0 = h2f(uA.x), c1 = h2f(uA.y), c2 = h2f(uA.z);
    float topr = a0.x + axA * (a1.y - a0.x);
    float topg = a0.y + axA * (a2.x - a0.y);
    float topb = a1.x + axA * (a2.y - a1.x);
    float botr = c0.x + axA * (c1.y - c0.x);
    float botg = c0.y + axA * (c2.x - c0.y);
    float botb = c1.x + axA * (c2.y - c1.x);

    float* oA = out + 3ull * (unsigned)i;
    oA[0] = topr + ayA * (botr - topr);
    oA[1] = topg + ayA * (botg - topg);
    oA[2] = topb + ayA * (botb - topb);

    // ---- pixel B ----
    float2 b0v = h2f(tB.x), b1v = h2f(tB.y), b2v = h2f(tB.z);
    float2 d0 = h2f(uB.x), d1 = h2f(uB.y), d2 = h2f(uB.z);
    float toprB = b0v.x + axB * (b1v.y - b0v.x);
    float topgB = b0v.y + axB * (b2v.x - b0v.y);
    float topbB = b1v.x + axB * (b2v.y - b1v.x);
    float botrB = d0.x + axB * (d1.y - d0.x);
    float botgB = d0.y + axB * (d2.x - d0.y);
    float botbB = d1.x + axB * (d2.y - d1.x);

    float* oB = out + 3ull * (unsigned)(i + NHALF);
    oB[0] = toprB + ayB * (botrB - toprB);
    oB[1] = topgB + ayB * (botgB - topgB);
    oB[2] = topbB + ayB * (botbB - topbB);
}

extern "C" void kernel_launch(void* const* d_in, const int* in_sizes, int n_in,
                              void* d_out, int out_size)
{
    const float* image = (const float*)d_in[0];
    const float* flow  = (const float*)d_in[1];
    float* out = (float*)d_out;

    const int threads = 256;

    pad_pair_kernel<<<(NPIX + threads - 1) / threads, threads>>>(image);
    warp_kernel<<<(NHALF + threads - 1) / threads, threads>>>(flow, out);
}